// round 13
// baseline (speedup 1.0000x reference)
#include <cuda_runtime.h>
#include <cstdint>

// Embedding gather: out[row, :] = weight[ids[row], :]
// ids: [8192] i32, weight: [32000, 1024] f32, out: [8192, 1024] f32.
//
// R8: roofline-confirmed LTS-cap kernel (~64MB through L2 @ ~6.3TB/s cap
// => ~10.5us floor). Structure: 4 rows/CTA, 512 threads; each thread moves
// one 32B chunk via LDG.256 (ld.global.nc.v8.b32) + two write-through
// STG.128 (__stwt). Grid = 2048, fully coalesced both directions.

#define DIM      1024
#define ROWS     4
#define THREADS  512          // 128 threads per row x 4 rows
#define TPR      128          // threads per row (128 * 32B = 4KB row)

struct v8 { uint32_t r[8]; };

__device__ __forceinline__ v8 ldg256(const void* p)
{
    v8 v;
    asm volatile(
        "ld.global.nc.v8.b32 {%0,%1,%2,%3,%4,%5,%6,%7}, [%8];"
        : "=r"(v.r[0]), "=r"(v.r[1]), "=r"(v.r[2]), "=r"(v.r[3]),
          "=r"(v.r[4]), "=r"(v.r[5]), "=r"(v.r[6]), "=r"(v.r[7])
        : "l"(p));
    return v;
}

__global__ void __launch_bounds__(THREADS, 4)
embed_gather_kernel(const int* __restrict__ ids,
                    const float* __restrict__ weight,
                    float* __restrict__ out)
{
    const int r    = threadIdx.x / TPR;            // row slot 0..3
    const int c    = (threadIdx.x % TPR) * 8;      // float offset (32B chunk)
    const int row  = blockIdx.x * ROWS + r;
    const int id   = __ldg(ids + row);

    const v8 v = ldg256(weight + (size_t)id * DIM + c);

    float4* dst = reinterpret_cast<float4*>(out + (size_t)row * DIM + c);
    __stwt(dst + 0, make_float4(__uint_as_float(v.r[0]), __uint_as_float(v.r[1]),
                                __uint_as_float(v.r[2]), __uint_as_float(v.r[3])));
    __stwt(dst + 1, make_float4(__uint_as_float(v.r[4]), __uint_as_float(v.r[5]),
                                __uint_as_float(v.r[6]), __uint_as_float(v.r[7])));
}

extern "C" void kernel_launch(void* const* d_in, const int* in_sizes, int n_in,
                              void* d_out, int out_size)
{
    const int*   ids    = (const int*)d_in[0];
    const float* weight = (const float*)d_in[1];
    float*       out    = (float*)d_out;

    const int n_rows = in_sizes[0];        // 8192
    const int grid   = n_rows / ROWS;      // 2048

    embed_gather_kernel<<<grid, THREADS>>>(ids, weight, out);
}

// round 14
// speedup vs baseline: 1.4102x; 1.4102x over previous
#include <cuda_runtime.h>

// Embedding gather: out[row, :] = weight[ids[row], :]
// ids: [8192] int32, weight: [32000, 1024] f32, out: [8192, 1024] f32.
//
// FINAL (= R7, best measured: 10.72us). Roofline analysis: 64MB compulsory
// L2-side traffic (32MB gathered reads, L2-resident steady-state + 32MB
// stores) at the path-independent LTS cap (~6.0-6.3 TB/s) gives a ~10.5us
// floor; this kernel sits at 98% of it. Verified dead ends: TMA bulk paths
// (=neutral), MLP batching (=neutral), evict_last hints (=neutral/worse),
// LDG.256 (-40%, L1tex replay penalty), wave-shaping (=neutral).
//
// Structure: one CTA per output row; 256 threads x float4 = one 1024-float
// row. Fully coalesced 128B transactions; write-through stores keep the
// never-re-read output from churning L2 dirty lines.

#define DIM 1024
#define VEC (DIM / 4)   // 256 float4 per row

__global__ void __launch_bounds__(256, 8)
embed_gather_kernel(const int* __restrict__ ids,
                    const float* __restrict__ weight,
                    float* __restrict__ out)
{
    const int row = blockIdx.x;
    const int id  = __ldg(ids + row);

    const float4* __restrict__ src =
        reinterpret_cast<const float4*>(weight) + (size_t)id * VEC;
    float4* __restrict__ dst =
        reinterpret_cast<float4*>(out) + (size_t)row * VEC;

    const float4 v = __ldg(src + threadIdx.x);
    __stwt(dst + threadIdx.x, v);
}

extern "C" void kernel_launch(void* const* d_in, const int* in_sizes, int n_in,
                              void* d_out, int out_size)
{
    // metadata order: input_ids (int32, 4*2048), weight (float32, 32000*1024)
    const int*   ids    = (const int*)d_in[0];
    const float* weight = (const float*)d_in[1];
    float*       out    = (float*)d_out;

    const int n_rows = in_sizes[0];   // 8192

    embed_gather_kernel<<<n_rows, 256>>>(ids, weight, out);
}